// round 2
// baseline (speedup 1.0000x reference)
#include <cuda_runtime.h>

#define NROWS 2048
#define DIM   1024
#define KCENT 256
#define GRID  592
#define TPB   256

// skewed index: spread binary-search address sets across smem banks
__device__ __forceinline__ int skew(int i) { return i + (i >> 5); }

__global__ __launch_bounds__(TPB)
void planar_quant_kernel(const float* __restrict__ x,
                         const float* __restrict__ centroids,
                         const float* __restrict__ rot2,
                         float* __restrict__ out_xhat,
                         float* __restrict__ out_idx,
                         int write_idx) {
    __shared__ float smid[KCENT + (KCENT >> 5)];   // midpoints (skewed), m[255]=+inf
    __shared__ float scen[KCENT + (KCENT >> 5)];   // centroids (skewed)
    __shared__ float sred[2][8];

    const int t = threadIdx.x;

    // build tables once per CTA
    if (t < KCENT) {
        float c = centroids[t];
        scen[skew(t)] = c;
        smid[skew(t)] = (t < KCENT - 1)
                        ? 0.5f * (c + centroids[t + 1])
                        : __int_as_float(0x7f800000);   // +inf sentinel
    }

    // rotation params for groups 2t, 2t+1 — invariant across rows, load once
    const float4 rv = reinterpret_cast<const float4*>(rot2)[t];

    int row = blockIdx.x;
    // prefetch first row
    float4 xv = reinterpret_cast<const float4*>(x + (size_t)row * DIM)[t];
    int buf = 0;

    for (; row < NROWS; row += GRID) {
        // prefetch next row early; overlaps with the search chain below
        const int nrow = row + GRID;
        float4 nxt;
        if (nrow < NROWS)
            nxt = reinterpret_cast<const float4*>(x + (size_t)nrow * DIM)[t];

        // block sum of squares
        float ss = xv.x * xv.x + xv.y * xv.y + xv.z * xv.z + xv.w * xv.w;
        #pragma unroll
        for (int o = 16; o; o >>= 1) ss += __shfl_xor_sync(0xffffffffu, ss, o);
        if ((t & 31) == 0) sred[buf][t >> 5] = ss;
        __syncthreads();   // also covers table init before first use

        float total = 0.f;
        #pragma unroll
        for (int i = 0; i < 8; i++) total += sred[buf][i];

        float norm = fmaxf(sqrtf(total), 1e-8f);
        const float rn = 1.0f / norm;

        const float v0 = xv.x * rn, v1 = xv.y * rn;
        const float v2 = xv.z * rn, v3 = xv.w * rn;

        const float r0 = rv.x * v0 - rv.y * v1;
        const float r1 = rv.y * v0 + rv.x * v1;
        const float r2 = rv.z * v2 - rv.w * v3;
        const float r3 = rv.w * v2 + rv.z * v3;

        // idx = #{midpoints < v}; tie at midpoint -> lower index (argmin semantics)
        int p0 = 0, p1 = 0, p2 = 0, p3 = 0;
        #pragma unroll
        for (int s = 128; s; s >>= 1) {
            if (smid[skew(p0 + s - 1)] < r0) p0 += s;
            if (smid[skew(p1 + s - 1)] < r1) p1 += s;
            if (smid[skew(p2 + s - 1)] < r2) p2 += s;
            if (smid[skew(p3 + s - 1)] < r3) p3 += s;
        }
        const float q0 = scen[skew(p0)];
        const float q1 = scen[skew(p1)];
        const float q2 = scen[skew(p2)];
        const float q3 = scen[skew(p3)];

        // inverse rotation, rescale
        float4 xh;
        xh.x = ( rv.x * q0 + rv.y * q1) * norm;
        xh.y = (-rv.y * q0 + rv.x * q1) * norm;
        xh.z = ( rv.z * q2 + rv.w * q3) * norm;
        xh.w = (-rv.w * q2 + rv.z * q3) * norm;
        reinterpret_cast<float4*>(out_xhat + (size_t)row * DIM)[t] = xh;

        if (write_idx) {
            float4 fi;
            fi.x = (float)p0; fi.y = (float)p1; fi.z = (float)p2; fi.w = (float)p3;
            reinterpret_cast<float4*>(out_idx + (size_t)row * DIM)[t] = fi;
        }

        xv = nxt;
        buf ^= 1;
    }
}

extern "C" void kernel_launch(void* const* d_in, const int* in_sizes, int n_in,
                              void* d_out, int out_size) {
    const float* x         = (const float*)d_in[0];  // [2048, 1024]
    const float* centroids = (const float*)d_in[1];  // [256]
    const float* rot2      = (const float*)d_in[2];  // [512, 2]

    float* out = (float*)d_out;
    const int full = (out_size >= 2 * NROWS * DIM);
    float* out_xhat = out;
    float* out_idx  = full ? out + (size_t)NROWS * DIM : out;

    planar_quant_kernel<<<GRID, TPB>>>(x, centroids, rot2,
                                       out_xhat, out_idx, full);
}

// round 3
// speedup vs baseline: 1.0226x; 1.0226x over previous
#include <cuda_runtime.h>
#include <math_constants.h>

#define NROWS 2048
#define DIM   1024
#define KCENT 256
#define NB    2048
#define TPB   256

__global__ __launch_bounds__(TPB)
void planar_quant_kernel(const float* __restrict__ x,
                         const float* __restrict__ centroids,
                         const float* __restrict__ rot2,
                         float* __restrict__ out_xhat,
                         float* __restrict__ out_idx,
                         int write_idx) {
    __shared__ float scen[KCENT];       // centroids
    __shared__ float smid[KCENT];       // midpoints, smid[255] = +inf sentinel
    __shared__ int   lut[NB];           // lower-bound index per uniform bin
    __shared__ float sred[8];           // norm reduction partials
    __shared__ int   swsum[8];          // scan warp totals

    const int t    = threadIdx.x;
    const int row  = blockIdx.x;
    const int lane = t & 31;
    const int wid  = t >> 5;

    // ---- long-latency global loads first ----
    const float4 xv = reinterpret_cast<const float4*>(x + (size_t)row * DIM)[t];
    const float4 rv = reinterpret_cast<const float4*>(rot2)[t];
    const float  c0 = centroids[t];
    const float  c1 = centroids[t < KCENT - 1 ? t + 1 : KCENT - 1];

    // ---- build tables, zero histogram ----
    const float mid = (t < KCENT - 1) ? 0.5f * (c0 + c1) : CUDART_INF_F;
    scen[t] = c0;
    smid[t] = mid;
    {
        int4 z = make_int4(0, 0, 0, 0);
        reinterpret_cast<int4*>(lut)[2 * t]     = z;
        reinterpret_cast<int4*>(lut)[2 * t + 1] = z;
    }

    // ---- norm partial reduction (independent of smem tables) ----
    float ss = xv.x * xv.x + xv.y * xv.y + xv.z * xv.z + xv.w * xv.w;
    #pragma unroll
    for (int o = 16; o; o >>= 1) ss += __shfl_xor_sync(0xffffffffu, ss, o);
    if (lane == 0) sred[wid] = ss;

    __syncthreads();

    // ---- binning transform (identical op for midpoints and queries) ----
    const float lo    = smid[0];
    const float hi    = smid[KCENT - 2];
    const float scale = (float)NB / fmaxf(hi - lo, 1e-30f);
    const float bias  = -lo * scale;

    // ---- histogram of midpoint bins ----
    if (t < KCENT - 1) {
        float bf = fmaf(mid, scale, bias);
        int b = (int)fminf(fmaxf(bf, 0.0f), (float)(NB - 1));
        atomicAdd(&lut[b], 1);
    }
    __syncthreads();

    // ---- exclusive prefix scan over 2048 bins (8 bins/thread, in place) ----
    int4 h0 = reinterpret_cast<int4*>(lut)[2 * t];
    int4 h1 = reinterpret_cast<int4*>(lut)[2 * t + 1];
    const int hsum = h0.x + h0.y + h0.z + h0.w + h1.x + h1.y + h1.z + h1.w;
    int inc = hsum;
    #pragma unroll
    for (int o = 1; o < 32; o <<= 1) {
        int n = __shfl_up_sync(0xffffffffu, inc, o);
        if (lane >= o) inc += n;
    }
    if (lane == 31) swsum[wid] = inc;
    __syncthreads();

    int base = inc - hsum;                        // exclusive within warp
    #pragma unroll
    for (int i = 0; i < 8; i++)
        if (i < wid) base += swsum[i];

    int4 e0, e1;
    e0.x = base;
    e0.y = e0.x + h0.x;  e0.z = e0.y + h0.y;  e0.w = e0.z + h0.z;
    e1.x = e0.w + h0.w;  e1.y = e1.x + h1.x;  e1.z = e1.y + h1.y;  e1.w = e1.z + h1.z;
    reinterpret_cast<int4*>(lut)[2 * t]     = e0;   // each thread rewrites only its own bins
    reinterpret_cast<int4*>(lut)[2 * t + 1] = e1;
    __syncthreads();

    // ---- finish norm ----
    float4 s0 = reinterpret_cast<float4*>(sred)[0];
    float4 s1 = reinterpret_cast<float4*>(sred)[1];
    float total = (s0.x + s0.y) + (s0.z + s0.w) + (s1.x + s1.y) + (s1.z + s1.w);
    const float norm = fmaxf(sqrtf(total), 1e-8f);
    const float rn   = 1.0f / norm;

    // ---- rotate ----
    const float v0 = xv.x * rn, v1 = xv.y * rn;
    const float v2 = xv.z * rn, v3 = xv.w * rn;
    const float r0 = rv.x * v0 - rv.y * v1;
    const float r1 = rv.y * v0 + rv.x * v1;
    const float r2 = rv.z * v2 - rv.w * v3;
    const float r3 = rv.w * v2 + rv.z * v3;

    // ---- quantize: LUT lower bound + exact walk (argmin semantics) ----
    auto quant = [&](float v) -> int {
        float bf = fmaf(v, scale, bias);
        int b = (int)fminf(fmaxf(bf, 0.0f), (float)(NB - 1));
        int idx = lut[b];
        idx += (smid[idx] < v);
        idx += (smid[idx] < v);
        while (smid[idx] < v) idx++;   // rare; smid[255]=+inf terminates
        return idx;
    };
    const int i0 = quant(r0);
    const int i1 = quant(r1);
    const int i2 = quant(r2);
    const int i3 = quant(r3);

    const float q0 = scen[i0], q1 = scen[i1], q2 = scen[i2], q3 = scen[i3];

    // ---- inverse rotate, rescale, store ----
    float4 xh;
    xh.x = ( rv.x * q0 + rv.y * q1) * norm;
    xh.y = (-rv.y * q0 + rv.x * q1) * norm;
    xh.z = ( rv.z * q2 + rv.w * q3) * norm;
    xh.w = (-rv.w * q2 + rv.z * q3) * norm;
    reinterpret_cast<float4*>(out_xhat + (size_t)row * DIM)[t] = xh;

    if (write_idx) {
        float4 fi;
        fi.x = (float)i0; fi.y = (float)i1; fi.z = (float)i2; fi.w = (float)i3;
        reinterpret_cast<float4*>(out_idx + (size_t)row * DIM)[t] = fi;
    }
}

extern "C" void kernel_launch(void* const* d_in, const int* in_sizes, int n_in,
                              void* d_out, int out_size) {
    const float* x         = (const float*)d_in[0];  // [2048, 1024]
    const float* centroids = (const float*)d_in[1];  // [256]
    const float* rot2      = (const float*)d_in[2];  // [512, 2]

    float* out = (float*)d_out;
    const int full = (out_size >= 2 * NROWS * DIM);
    float* out_xhat = out;
    float* out_idx  = full ? out + (size_t)NROWS * DIM : out;

    planar_quant_kernel<<<NROWS, TPB>>>(x, centroids, rot2,
                                        out_xhat, out_idx, full);
}

// round 4
// speedup vs baseline: 1.2143x; 1.1875x over previous
#include <cuda_runtime.h>
#include <math_constants.h>

#define NROWS 2048
#define DIM   1024
#define KCENT 256
#define NB    1024
#define TPB   256
#define GRID  (NROWS / 2)   // 2 rows per CTA

__global__ __launch_bounds__(TPB)
void planar_quant_kernel(const float* __restrict__ x,
                         const float* __restrict__ centroids,
                         const float* __restrict__ rot2,
                         float* __restrict__ out_xhat,
                         float* __restrict__ out_idx,
                         int write_idx) {
    __shared__ float2 tab[KCENT];      // (midpoint, centroid); mid[255] = +inf
    __shared__ int    lut[NB];         // lower-bound index per uniform bin
    __shared__ float  sred[2][8];      // norm partials for the two rows
    __shared__ int    swsum[8];        // scan warp totals
    __shared__ float  srange[2];       // lo, hi midpoint

    const int t    = threadIdx.x;
    const int lane = t & 31;
    const int wid  = t >> 5;
    const int rowA = blockIdx.x * 2;
    const int rowB = rowA + 1;

    // ---- long-latency global loads first (MLP) ----
    const float4 xvA = reinterpret_cast<const float4*>(x + (size_t)rowA * DIM)[t];
    const float4 xvB = reinterpret_cast<const float4*>(x + (size_t)rowB * DIM)[t];
    const float4 rv  = reinterpret_cast<const float4*>(rot2)[t];
    const float  c0  = centroids[t];
    const float  c1  = centroids[t < KCENT - 1 ? t + 1 : KCENT - 1];

    // ---- tables + zero histogram ----
    const float mid = (t < KCENT - 1) ? 0.5f * (c0 + c1) : CUDART_INF_F;
    tab[t] = make_float2(mid, c0);
    reinterpret_cast<int4*>(lut)[t] = make_int4(0, 0, 0, 0);   // 4 bins/thread
    if (t == 0)         srange[0] = mid;
    if (t == KCENT - 2) srange[1] = mid;

    // ---- norm partials for both rows (independent of smem tables) ----
    float ssA = xvA.x * xvA.x + xvA.y * xvA.y + xvA.z * xvA.z + xvA.w * xvA.w;
    float ssB = xvB.x * xvB.x + xvB.y * xvB.y + xvB.z * xvB.z + xvB.w * xvB.w;
    #pragma unroll
    for (int o = 16; o; o >>= 1) {
        ssA += __shfl_xor_sync(0xffffffffu, ssA, o);
        ssB += __shfl_xor_sync(0xffffffffu, ssB, o);
    }
    if (lane == 0) { sred[0][wid] = ssA; sred[1][wid] = ssB; }

    __syncthreads();   // tables + zeroed lut + partials visible

    // ---- binning transform (same op for midpoints and queries) ----
    const float lo    = srange[0];
    const float hi    = srange[1];
    const float scale = (float)NB / fmaxf(hi - lo, 1e-30f);
    const float bias  = -lo * scale;

    // ---- histogram of midpoint bins ----
    if (t < KCENT - 1) {
        float bf = fmaf(mid, scale, bias);
        int b = (int)fminf(fmaxf(bf, 0.0f), (float)(NB - 1));
        atomicAdd(&lut[b], 1);
    }
    __syncthreads();

    // ---- exclusive prefix scan over NB bins (4 bins/thread, in place) ----
    int4 h = reinterpret_cast<int4*>(lut)[t];
    const int hsum = h.x + h.y + h.z + h.w;
    int inc = hsum;
    #pragma unroll
    for (int o = 1; o < 32; o <<= 1) {
        int n = __shfl_up_sync(0xffffffffu, inc, o);
        if (lane >= o) inc += n;
    }
    if (lane == 31) swsum[wid] = inc;
    __syncthreads();

    int base = inc - hsum;            // exclusive within warp
    #pragma unroll
    for (int i = 0; i < 8; i++)
        if (i < wid) base += swsum[i];

    int4 e;
    e.x = base;
    e.y = e.x + h.x;  e.z = e.y + h.y;  e.w = e.z + h.z;
    reinterpret_cast<int4*>(lut)[t] = e;    // each thread rewrites only its own bins
    __syncthreads();

    // ---- norms ----
    float4 a0 = reinterpret_cast<float4*>(sred[0])[0];
    float4 a1 = reinterpret_cast<float4*>(sred[0])[1];
    float4 b0 = reinterpret_cast<float4*>(sred[1])[0];
    float4 b1 = reinterpret_cast<float4*>(sred[1])[1];
    float totA = (a0.x + a0.y) + (a0.z + a0.w) + (a1.x + a1.y) + (a1.z + a1.w);
    float totB = (b0.x + b0.y) + (b0.z + b0.w) + (b1.x + b1.y) + (b1.z + b1.w);
    const float normA = fmaxf(sqrtf(totA), 1e-8f);
    const float normB = fmaxf(sqrtf(totB), 1e-8f);
    const float rnA = 1.0f / normA;
    const float rnB = 1.0f / normB;

    // ---- quantize: LUT lower bound + exact walk (argmin semantics) ----
    auto quant = [&](float v, int& idx, float& q) {
        float bf = fmaf(v, scale, bias);
        int b = (int)fminf(fmaxf(bf, 0.0f), (float)(NB - 1));
        int i = lut[b];
        float2 tc = tab[i];
        if (tc.x < v) { i++; tc = tab[i]; }
        if (tc.x < v) { i++; tc = tab[i]; }
        while (tc.x < v) { i++; tc = tab[i]; }   // rare; mid[255]=+inf terminates
        idx = i; q = tc.y;
    };

    #pragma unroll
    for (int r = 0; r < 2; r++) {
        const float4 xv  = r ? xvB : xvA;
        const float  rn  = r ? rnB : rnA;
        const float  nrm = r ? normB : normA;
        const int    row = r ? rowB : rowA;

        const float v0 = xv.x * rn, v1 = xv.y * rn;
        const float v2 = xv.z * rn, v3 = xv.w * rn;
        const float r0 = rv.x * v0 - rv.y * v1;
        const float r1 = rv.y * v0 + rv.x * v1;
        const float r2 = rv.z * v2 - rv.w * v3;
        const float r3 = rv.w * v2 + rv.z * v3;

        int   i0, i1, i2, i3;
        float q0, q1, q2, q3;
        quant(r0, i0, q0);
        quant(r1, i1, q1);
        quant(r2, i2, q2);
        quant(r3, i3, q3);

        float4 xh;
        xh.x = ( rv.x * q0 + rv.y * q1) * nrm;
        xh.y = (-rv.y * q0 + rv.x * q1) * nrm;
        xh.z = ( rv.z * q2 + rv.w * q3) * nrm;
        xh.w = (-rv.w * q2 + rv.z * q3) * nrm;
        reinterpret_cast<float4*>(out_xhat + (size_t)row * DIM)[t] = xh;

        if (write_idx) {
            float4 fi;
            fi.x = (float)i0; fi.y = (float)i1; fi.z = (float)i2; fi.w = (float)i3;
            reinterpret_cast<float4*>(out_idx + (size_t)row * DIM)[t] = fi;
        }
    }
}

extern "C" void kernel_launch(void* const* d_in, const int* in_sizes, int n_in,
                              void* d_out, int out_size) {
    const float* x         = (const float*)d_in[0];  // [2048, 1024]
    const float* centroids = (const float*)d_in[1];  // [256]
    const float* rot2      = (const float*)d_in[2];  // [512, 2]

    float* out = (float*)d_out;
    const int full = (out_size >= 2 * NROWS * DIM);
    float* out_xhat = out;
    float* out_idx  = full ? out + (size_t)NROWS * DIM : out;

    planar_quant_kernel<<<GRID, TPB>>>(x, centroids, rot2,
                                       out_xhat, out_idx, full);
}